// round 1
// baseline (speedup 1.0000x reference)
#include <cuda_runtime.h>
#include <cstdint>

// Problem constants (from reference setup_inputs)
#define NMAX 50000
#define F 128

// Scratch (allocation-free rule: __device__ globals)
__device__ float g_p[NMAX * F];     // relu(h @ W_pool + b_pool)
__device__ float g_agg[NMAX * F];   // segment max
__device__ float g_h1[NMAX * F];    // layer-1 output

// ---------------------------------------------------------------------------
// GEMM: C[M,128] = epilogue( A1[M,128] @ W1[128,128] (+ A2 @ W2) + bias )
// Tile: BM=64 x BN=128, BK=32. 256 threads, 4x8 micro-tile per thread.
// Epilogues: RELU, or L2-normalize rows then RELU (block owns whole rows).
// ---------------------------------------------------------------------------
#define BM 64
#define BK 32

template<bool RELU, bool L2N, bool TWO>
__global__ __launch_bounds__(256, 4)
void gemm128_kernel(const float* __restrict__ A1, const float* __restrict__ W1,
                    const float* __restrict__ A2, const float* __restrict__ W2,
                    const float* __restrict__ bias, float* __restrict__ C, int M)
{
    __shared__ float As[BK][BM + 4];   // [k][m], padded for bank/alignment
    __shared__ float Bs[BK][F];        // [k][n]
    __shared__ float rowsq[BM];

    const int tid = threadIdx.x;
    const int tx  = tid & 15;          // col group: 8 cols each
    const int ty  = tid >> 4;          // row group: 4 rows each
    const int m0  = blockIdx.x * BM;

    float acc[4][8];
#pragma unroll
    for (int i = 0; i < 4; i++)
#pragma unroll
        for (int j = 0; j < 8; j++) acc[i][j] = 0.0f;

#pragma unroll
    for (int pass = 0; pass < (TWO ? 2 : 1); pass++) {
        const float* __restrict__ A = (TWO && pass) ? A2 : A1;
        const float* __restrict__ W = (TWO && pass) ? W2 : W1;

        for (int kk = 0; kk < F; kk += BK) {
            __syncthreads();
            // --- load A tile (64 x 32), transposed into As[k][m] ---
#pragma unroll
            for (int i = 0; i < 2; i++) {
                int f4 = tid + i * 256;          // 512 float4 total
                int r  = f4 >> 3;                // 8 float4 per row
                int c4 = (f4 & 7) * 4;
                int m  = m0 + r;
                float4 v = make_float4(0.f, 0.f, 0.f, 0.f);
                if (m < M) v = *(const float4*)(A + (size_t)m * F + kk + c4);
                As[c4 + 0][r] = v.x;
                As[c4 + 1][r] = v.y;
                As[c4 + 2][r] = v.z;
                As[c4 + 3][r] = v.w;
            }
            // --- load W tile (32 x 128) ---
#pragma unroll
            for (int i = 0; i < 4; i++) {
                int f4 = tid + i * 256;          // 1024 float4 total
                int r  = f4 >> 5;                // 32 float4 per row
                int c4 = (f4 & 31) * 4;
                *(float4*)&Bs[r][c4] = *(const float4*)(W + (size_t)(kk + r) * F + c4);
            }
            __syncthreads();
            // --- compute ---
#pragma unroll
            for (int k = 0; k < BK; k++) {
                float4 a  = *(const float4*)&As[k][ty * 4];
                float4 b0 = *(const float4*)&Bs[k][tx * 8];
                float4 b1 = *(const float4*)&Bs[k][tx * 8 + 4];
                float av[4] = {a.x, a.y, a.z, a.w};
                float bv[8] = {b0.x, b0.y, b0.z, b0.w, b1.x, b1.y, b1.z, b1.w};
#pragma unroll
                for (int i = 0; i < 4; i++)
#pragma unroll
                    for (int j = 0; j < 8; j++)
                        acc[i][j] = fmaf(av[i], bv[j], acc[i][j]);
            }
        }
    }

    // --- epilogue ---
    float bv[8];
#pragma unroll
    for (int j = 0; j < 8; j++) bv[j] = bias[tx * 8 + j];

    if (L2N) {
        __syncthreads();
        if (tid < BM) rowsq[tid] = 0.0f;
        __syncthreads();
#pragma unroll
        for (int i = 0; i < 4; i++) {
            float s = 0.0f;
#pragma unroll
            for (int j = 0; j < 8; j++) {
                float h = acc[i][j] + bv[j];
                acc[i][j] = h;
                s = fmaf(h, h, s);
            }
            atomicAdd(&rowsq[ty * 4 + i], s);
        }
        __syncthreads();
#pragma unroll
        for (int i = 0; i < 4; i++) {
            int m = m0 + ty * 4 + i;
            float n = fmaxf(sqrtf(rowsq[ty * 4 + i]), 1e-12f);
            float inv = 1.0f / n;
            float4 o0, o1;
            o0.x = fmaxf(acc[i][0] * inv, 0.f);
            o0.y = fmaxf(acc[i][1] * inv, 0.f);
            o0.z = fmaxf(acc[i][2] * inv, 0.f);
            o0.w = fmaxf(acc[i][3] * inv, 0.f);
            o1.x = fmaxf(acc[i][4] * inv, 0.f);
            o1.y = fmaxf(acc[i][5] * inv, 0.f);
            o1.z = fmaxf(acc[i][6] * inv, 0.f);
            o1.w = fmaxf(acc[i][7] * inv, 0.f);
            if (m < M) {
                *(float4*)(C + (size_t)m * F + tx * 8)     = o0;
                *(float4*)(C + (size_t)m * F + tx * 8 + 4) = o1;
            }
        }
    } else {
#pragma unroll
        for (int i = 0; i < 4; i++) {
            int m = m0 + ty * 4 + i;
            if (m >= M) continue;
            float4 o0, o1;
            float h;
            h = acc[i][0] + bv[0]; o0.x = RELU ? fmaxf(h, 0.f) : h;
            h = acc[i][1] + bv[1]; o0.y = RELU ? fmaxf(h, 0.f) : h;
            h = acc[i][2] + bv[2]; o0.z = RELU ? fmaxf(h, 0.f) : h;
            h = acc[i][3] + bv[3]; o0.w = RELU ? fmaxf(h, 0.f) : h;
            h = acc[i][4] + bv[4]; o1.x = RELU ? fmaxf(h, 0.f) : h;
            h = acc[i][5] + bv[5]; o1.y = RELU ? fmaxf(h, 0.f) : h;
            h = acc[i][6] + bv[6]; o1.z = RELU ? fmaxf(h, 0.f) : h;
            h = acc[i][7] + bv[7]; o1.w = RELU ? fmaxf(h, 0.f) : h;
            *(float4*)(C + (size_t)m * F + tx * 8)     = o0;
            *(float4*)(C + (size_t)m * F + tx * 8 + 4) = o1;
        }
    }
}

// ---------------------------------------------------------------------------
// Scatter max: one warp per edge, 4 floats per lane.
// p >= 0 (post-relu) so int-bit atomicMax == float max; agg pre-zeroed, and
// v == 0 contributes nothing -> skip (halves atomic traffic).
// ---------------------------------------------------------------------------
__global__ void scatter_max_kernel(const float* __restrict__ p,
                                   const int* __restrict__ src,
                                   const int* __restrict__ dst,
                                   float* __restrict__ agg, int E)
{
    long long gid = (long long)blockIdx.x * blockDim.x + threadIdx.x;
    int e = (int)(gid >> 5);
    int lane = (int)(gid & 31);
    if (e >= E) return;
    int s = __ldg(&src[e]);
    int d = __ldg(&dst[e]);
    float4 v = *(const float4*)(p + (size_t)s * F + lane * 4);
    int* a = (int*)(agg + (size_t)d * F + lane * 4);
    if (v.x > 0.f) atomicMax(a + 0, __float_as_int(v.x));
    if (v.y > 0.f) atomicMax(a + 1, __float_as_int(v.y));
    if (v.z > 0.f) atomicMax(a + 2, __float_as_int(v.z));
    if (v.w > 0.f) atomicMax(a + 3, __float_as_int(v.w));
}

// ---------------------------------------------------------------------------
extern "C" void kernel_launch(void* const* d_in, const int* in_sizes, int n_in,
                              void* d_out, int out_size)
{
    const float* x       = (const float*)d_in[0];
    const int*   src     = (const int*)  d_in[1];
    const int*   dst     = (const int*)  d_in[2];
    const float* W_pool1 = (const float*)d_in[3];
    const float* b_pool1 = (const float*)d_in[4];
    const float* W_self1 = (const float*)d_in[5];
    const float* W_neigh1= (const float*)d_in[6];
    const float* b1      = (const float*)d_in[7];
    const float* W_pool2 = (const float*)d_in[8];
    const float* b_pool2 = (const float*)d_in[9];
    const float* W_self2 = (const float*)d_in[10];
    const float* W_neigh2= (const float*)d_in[11];
    const float* b2      = (const float*)d_in[12];

    const int M = in_sizes[0] / F;       // 50000
    const int E = in_sizes[1];           // 1600000

    float *p, *agg, *h1;
    cudaGetSymbolAddress((void**)&p,   g_p);
    cudaGetSymbolAddress((void**)&agg, g_agg);
    cudaGetSymbolAddress((void**)&h1,  g_h1);
    float* out = (float*)d_out;

    const int gblocks = (M + BM - 1) / BM;
    const long long sthreads = (long long)E * 32;
    const int sblocks = (int)((sthreads + 255) / 256);
    const size_t aggBytes = (size_t)M * F * sizeof(float);

    // ---- Layer 1 ----
    gemm128_kernel<true, false, false><<<gblocks, 256>>>(x, W_pool1, nullptr, nullptr, b_pool1, p, M);
    cudaMemsetAsync(agg, 0, aggBytes, 0);
    scatter_max_kernel<<<sblocks, 256>>>(p, src, dst, agg, E);
    gemm128_kernel<false, true, true><<<gblocks, 256>>>(x, W_self1, agg, W_neigh1, b1, h1, M);

    // ---- Layer 2 ----
    gemm128_kernel<true, false, false><<<gblocks, 256>>>(h1, W_pool2, nullptr, nullptr, b_pool2, p, M);
    cudaMemsetAsync(agg, 0, aggBytes, 0);
    scatter_max_kernel<<<sblocks, 256>>>(p, src, dst, agg, E);
    gemm128_kernel<false, true, true><<<gblocks, 256>>>(h1, W_self2, agg, W_neigh2, b2, out, M);
}

// round 2
// speedup vs baseline: 1.8720x; 1.8720x over previous
#include <cuda_runtime.h>
#include <cstdint>

// Problem constants (from reference setup_inputs)
#define NMAX 50048
#define EMAX 1600000
#define F 128

// Scratch (allocation-free rule: __device__ globals)
__device__ float g_p[NMAX * F];     // relu(h @ W_pool + b_pool)
__device__ float g_agg[NMAX * F];   // segment max
__device__ float g_h1[NMAX * F];    // layer-1 output

// CSR-by-dst scratch
__device__ int g_cnt[NMAX];         // per-dst in-degree
__device__ int g_rowptr[NMAX + 1];  // exclusive prefix
__device__ int g_cursor[NMAX];      // fill cursors
__device__ int g_eidx[EMAX];        // src node per CSR slot
__device__ int g_blksum[64];        // scan partials

// ---------------------------------------------------------------------------
// GEMM: C[M,128] = epilogue( A1[M,128] @ W1[128,128] (+ A2 @ W2) + bias )
// Tile: BM=64 x BN=128, BK=32. 256 threads, 4x8 micro-tile per thread.
// ---------------------------------------------------------------------------
#define BM 64
#define BK 32

template<bool RELU, bool L2N, bool TWO>
__global__ __launch_bounds__(256, 4)
void gemm128_kernel(const float* __restrict__ A1, const float* __restrict__ W1,
                    const float* __restrict__ A2, const float* __restrict__ W2,
                    const float* __restrict__ bias, float* __restrict__ C, int M)
{
    __shared__ float As[BK][BM + 4];   // [k][m]
    __shared__ float Bs[BK][F];        // [k][n]
    __shared__ float rowsq[BM];

    const int tid = threadIdx.x;
    const int tx  = tid & 15;          // col group: 8 cols each
    const int ty  = tid >> 4;          // row group: 4 rows each
    const int m0  = blockIdx.x * BM;

    float acc[4][8];
#pragma unroll
    for (int i = 0; i < 4; i++)
#pragma unroll
        for (int j = 0; j < 8; j++) acc[i][j] = 0.0f;

#pragma unroll
    for (int pass = 0; pass < (TWO ? 2 : 1); pass++) {
        const float* __restrict__ A = (TWO && pass) ? A2 : A1;
        const float* __restrict__ W = (TWO && pass) ? W2 : W1;

        for (int kk = 0; kk < F; kk += BK) {
            __syncthreads();
            // --- load A tile (64 x 32), transposed into As[k][m] ---
#pragma unroll
            for (int i = 0; i < 2; i++) {
                int f4 = tid + i * 256;          // 512 float4 total
                int r  = f4 >> 3;                // 8 float4 per row
                int c4 = (f4 & 7) * 4;
                int m  = m0 + r;
                float4 v = make_float4(0.f, 0.f, 0.f, 0.f);
                if (m < M) v = *(const float4*)(A + (size_t)m * F + kk + c4);
                As[c4 + 0][r] = v.x;
                As[c4 + 1][r] = v.y;
                As[c4 + 2][r] = v.z;
                As[c4 + 3][r] = v.w;
            }
            // --- load W tile (32 x 128) ---
#pragma unroll
            for (int i = 0; i < 4; i++) {
                int f4 = tid + i * 256;          // 1024 float4 total
                int r  = f4 >> 5;                // 32 float4 per row
                int c4 = (f4 & 31) * 4;
                *(float4*)&Bs[r][c4] = *(const float4*)(W + (size_t)(kk + r) * F + c4);
            }
            __syncthreads();
            // --- compute ---
#pragma unroll
            for (int k = 0; k < BK; k++) {
                float4 a  = *(const float4*)&As[k][ty * 4];
                float4 b0 = *(const float4*)&Bs[k][tx * 8];
                float4 b1 = *(const float4*)&Bs[k][tx * 8 + 4];
                float av[4] = {a.x, a.y, a.z, a.w};
                float bv[8] = {b0.x, b0.y, b0.z, b0.w, b1.x, b1.y, b1.z, b1.w};
#pragma unroll
                for (int i = 0; i < 4; i++)
#pragma unroll
                    for (int j = 0; j < 8; j++)
                        acc[i][j] = fmaf(av[i], bv[j], acc[i][j]);
            }
        }
    }

    // --- epilogue ---
    float bv[8];
#pragma unroll
    for (int j = 0; j < 8; j++) bv[j] = bias[tx * 8 + j];

    if (L2N) {
        __syncthreads();
        if (tid < BM) rowsq[tid] = 0.0f;
        __syncthreads();
#pragma unroll
        for (int i = 0; i < 4; i++) {
            float s = 0.0f;
#pragma unroll
            for (int j = 0; j < 8; j++) {
                float h = acc[i][j] + bv[j];
                acc[i][j] = h;
                s = fmaf(h, h, s);
            }
            atomicAdd(&rowsq[ty * 4 + i], s);
        }
        __syncthreads();
#pragma unroll
        for (int i = 0; i < 4; i++) {
            int m = m0 + ty * 4 + i;
            float n = fmaxf(sqrtf(rowsq[ty * 4 + i]), 1e-12f);
            float inv = 1.0f / n;
            float4 o0, o1;
            o0.x = fmaxf(acc[i][0] * inv, 0.f);
            o0.y = fmaxf(acc[i][1] * inv, 0.f);
            o0.z = fmaxf(acc[i][2] * inv, 0.f);
            o0.w = fmaxf(acc[i][3] * inv, 0.f);
            o1.x = fmaxf(acc[i][4] * inv, 0.f);
            o1.y = fmaxf(acc[i][5] * inv, 0.f);
            o1.z = fmaxf(acc[i][6] * inv, 0.f);
            o1.w = fmaxf(acc[i][7] * inv, 0.f);
            if (m < M) {
                *(float4*)(C + (size_t)m * F + tx * 8)     = o0;
                *(float4*)(C + (size_t)m * F + tx * 8 + 4) = o1;
            }
        }
    } else {
#pragma unroll
        for (int i = 0; i < 4; i++) {
            int m = m0 + ty * 4 + i;
            if (m >= M) continue;
            float4 o0, o1;
            float h;
            h = acc[i][0] + bv[0]; o0.x = RELU ? fmaxf(h, 0.f) : h;
            h = acc[i][1] + bv[1]; o0.y = RELU ? fmaxf(h, 0.f) : h;
            h = acc[i][2] + bv[2]; o0.z = RELU ? fmaxf(h, 0.f) : h;
            h = acc[i][3] + bv[3]; o0.w = RELU ? fmaxf(h, 0.f) : h;
            h = acc[i][4] + bv[4]; o1.x = RELU ? fmaxf(h, 0.f) : h;
            h = acc[i][5] + bv[5]; o1.y = RELU ? fmaxf(h, 0.f) : h;
            h = acc[i][6] + bv[6]; o1.z = RELU ? fmaxf(h, 0.f) : h;
            h = acc[i][7] + bv[7]; o1.w = RELU ? fmaxf(h, 0.f) : h;
            *(float4*)(C + (size_t)m * F + tx * 8)     = o0;
            *(float4*)(C + (size_t)m * F + tx * 8 + 4) = o1;
        }
    }
}

// ---------------------------------------------------------------------------
// CSR-by-dst build
// ---------------------------------------------------------------------------
__global__ void hist_kernel(const int* __restrict__ dst, int* __restrict__ cnt, int E)
{
    int e = blockIdx.x * blockDim.x + threadIdx.x;
    if (e < E) atomicAdd(&cnt[dst[e]], 1);
}

#define SCAN_CHUNK 1024
__global__ void scan_block_kernel(const int* __restrict__ cnt, int* __restrict__ rowptr,
                                  int* __restrict__ blksum, int N)
{
    __shared__ int s[SCAN_CHUNK];
    int i = blockIdx.x * SCAN_CHUNK + threadIdx.x;
    int v = (i < N) ? cnt[i] : 0;
    s[threadIdx.x] = v;
    __syncthreads();
#pragma unroll
    for (int off = 1; off < SCAN_CHUNK; off <<= 1) {
        int t = (threadIdx.x >= off) ? s[threadIdx.x - off] : 0;
        __syncthreads();
        s[threadIdx.x] += t;
        __syncthreads();
    }
    if (i < N) rowptr[i] = s[threadIdx.x] - v;   // exclusive within chunk
    if (threadIdx.x == SCAN_CHUNK - 1) blksum[blockIdx.x] = s[threadIdx.x];
}

__global__ void scan_partials_kernel(int* blksum, int nb)
{
    if (threadIdx.x == 0 && blockIdx.x == 0) {
        int acc = 0;
        for (int i = 0; i < nb; i++) { int t = blksum[i]; blksum[i] = acc; acc += t; }
    }
}

__global__ void add_offsets_kernel(int* __restrict__ rowptr, int* __restrict__ cursor,
                                   const int* __restrict__ blksum, int N, int E)
{
    int i = blockIdx.x * blockDim.x + threadIdx.x;
    if (i < N) {
        int v = rowptr[i] + blksum[i >> 10];
        rowptr[i] = v;
        cursor[i] = v;
    }
    if (i == N) rowptr[N] = E;
}

__global__ void fill_csr_kernel(const int* __restrict__ src, const int* __restrict__ dst,
                                int* __restrict__ cursor, int* __restrict__ eidx, int E)
{
    int e = blockIdx.x * blockDim.x + threadIdx.x;
    if (e < E) {
        int pos = atomicAdd(&cursor[dst[e]], 1);
        eidx[pos] = src[e];
    }
}

// ---------------------------------------------------------------------------
// Gather-max: one warp per dst node, lane owns 4 contiguous features (float4).
// Coalesced 512B row reads from L2-resident p; no atomics; empty node -> 0.
// ---------------------------------------------------------------------------
__global__ void gather_max_kernel(const float* __restrict__ p,
                                  const int* __restrict__ rowptr,
                                  const int* __restrict__ eidx,
                                  float* __restrict__ agg, int N)
{
    int warp = (blockIdx.x * blockDim.x + threadIdx.x) >> 5;
    int lane = threadIdx.x & 31;
    if (warp >= N) return;
    int beg = __ldg(&rowptr[warp]);
    int end = __ldg(&rowptr[warp + 1]);

    float4 acc = make_float4(0.f, 0.f, 0.f, 0.f);
    int i = beg;
    for (; i + 3 < end; i += 4) {
        int s0 = __ldg(&eidx[i]);
        int s1 = __ldg(&eidx[i + 1]);
        int s2 = __ldg(&eidx[i + 2]);
        int s3 = __ldg(&eidx[i + 3]);
        float4 v0 = *(const float4*)(p + (size_t)s0 * F + lane * 4);
        float4 v1 = *(const float4*)(p + (size_t)s1 * F + lane * 4);
        float4 v2 = *(const float4*)(p + (size_t)s2 * F + lane * 4);
        float4 v3 = *(const float4*)(p + (size_t)s3 * F + lane * 4);
        acc.x = fmaxf(acc.x, fmaxf(fmaxf(v0.x, v1.x), fmaxf(v2.x, v3.x)));
        acc.y = fmaxf(acc.y, fmaxf(fmaxf(v0.y, v1.y), fmaxf(v2.y, v3.y)));
        acc.z = fmaxf(acc.z, fmaxf(fmaxf(v0.z, v1.z), fmaxf(v2.z, v3.z)));
        acc.w = fmaxf(acc.w, fmaxf(fmaxf(v0.w, v1.w), fmaxf(v2.w, v3.w)));
    }
    for (; i < end; i++) {
        int s = __ldg(&eidx[i]);
        float4 v = *(const float4*)(p + (size_t)s * F + lane * 4);
        acc.x = fmaxf(acc.x, v.x);
        acc.y = fmaxf(acc.y, v.y);
        acc.z = fmaxf(acc.z, v.z);
        acc.w = fmaxf(acc.w, v.w);
    }
    *(float4*)(agg + (size_t)warp * F + lane * 4) = acc;
}

// ---------------------------------------------------------------------------
extern "C" void kernel_launch(void* const* d_in, const int* in_sizes, int n_in,
                              void* d_out, int out_size)
{
    const float* x       = (const float*)d_in[0];
    const int*   src     = (const int*)  d_in[1];
    const int*   dst     = (const int*)  d_in[2];
    const float* W_pool1 = (const float*)d_in[3];
    const float* b_pool1 = (const float*)d_in[4];
    const float* W_self1 = (const float*)d_in[5];
    const float* W_neigh1= (const float*)d_in[6];
    const float* b1      = (const float*)d_in[7];
    const float* W_pool2 = (const float*)d_in[8];
    const float* b_pool2 = (const float*)d_in[9];
    const float* W_self2 = (const float*)d_in[10];
    const float* W_neigh2= (const float*)d_in[11];
    const float* b2      = (const float*)d_in[12];

    const int M = in_sizes[0] / F;       // 50000
    const int E = in_sizes[1];           // 1600000

    float *p, *agg, *h1;
    int *cnt, *rowptr, *cursor, *eidx, *blksum;
    cudaGetSymbolAddress((void**)&p,      g_p);
    cudaGetSymbolAddress((void**)&agg,    g_agg);
    cudaGetSymbolAddress((void**)&h1,     g_h1);
    cudaGetSymbolAddress((void**)&cnt,    g_cnt);
    cudaGetSymbolAddress((void**)&rowptr, g_rowptr);
    cudaGetSymbolAddress((void**)&cursor, g_cursor);
    cudaGetSymbolAddress((void**)&eidx,   g_eidx);
    cudaGetSymbolAddress((void**)&blksum, g_blksum);
    float* out = (float*)d_out;

    const int gblocks = (M + BM - 1) / BM;
    const int eblocks = (E + 255) / 256;
    const int nb      = (M + SCAN_CHUNK - 1) / SCAN_CHUNK;
    const int wblocks = (M * 32 + 255) / 256;   // gather: 1 warp/node

    // ---- CSR build (once, serves both layers) ----
    cudaMemsetAsync(cnt, 0, (size_t)M * sizeof(int), 0);
    hist_kernel<<<eblocks, 256>>>(dst, cnt, E);
    scan_block_kernel<<<nb, SCAN_CHUNK>>>(cnt, rowptr, blksum, M);
    scan_partials_kernel<<<1, 32>>>(blksum, nb);
    add_offsets_kernel<<<(M + 256) / 256, 256>>>(rowptr, cursor, blksum, M, E);
    fill_csr_kernel<<<eblocks, 256>>>(src, dst, cursor, eidx, E);

    // ---- Layer 1 ----
    gemm128_kernel<true, false, false><<<gblocks, 256>>>(x, W_pool1, nullptr, nullptr, b_pool1, p, M);
    gather_max_kernel<<<wblocks, 256>>>(p, rowptr, eidx, agg, M);
    gemm128_kernel<false, true, true><<<gblocks, 256>>>(x, W_self1, agg, W_neigh1, b1, h1, M);

    // ---- Layer 2 ----
    gemm128_kernel<true, false, false><<<gblocks, 256>>>(h1, W_pool2, nullptr, nullptr, b_pool2, p, M);
    gather_max_kernel<<<wblocks, 256>>>(p, rowptr, eidx, agg, M);
    gemm128_kernel<false, true, true><<<gblocks, 256>>>(h1, W_self2, agg, W_neigh2, b2, out, M);
}

// round 3
// speedup vs baseline: 4.0127x; 2.1435x over previous
#include <cuda_runtime.h>
#include <cstdint>

// Problem constants (from reference setup_inputs)
#define NMAX 50048
#define EMAX 1600000
#define F 128

// Scratch (allocation-free rule: __device__ globals)
__device__ float g_p[NMAX * F];     // relu(h @ W_pool + b_pool), tf32-rounded
__device__ float g_agg[NMAX * F];   // segment max (already tf32-rounded values)
__device__ float g_h1[NMAX * F];    // layer-1 output, tf32-rounded
__device__ float g_xr[NMAX * F];    // tf32-rounded copy of x
__device__ float g_w[6 * F * F];    // tf32-rounded weights

// CSR-by-dst scratch
__device__ int g_cnt[NMAX];
__device__ int g_rowptr[NMAX + 1];
__device__ int g_cursor[NMAX];
__device__ int g_eidx[EMAX];
__device__ int g_blksum[64];

// ---------------------------------------------------------------------------
// Helpers
// ---------------------------------------------------------------------------
__device__ __forceinline__ float tf32_rna(float x) {
    unsigned u;
    asm("cvt.rna.tf32.f32 %0, %1;" : "=r"(u) : "f"(x));
    return __uint_as_float(u);
}

__device__ __forceinline__ void cp16(void* smem_dst, const void* gsrc) {
    unsigned d = (unsigned)__cvta_generic_to_shared(smem_dst);
    asm volatile("cp.async.cg.shared.global [%0], [%1], 16;" :: "r"(d), "l"(gsrc));
}
#define CP_COMMIT() asm volatile("cp.async.commit_group;")
#define CP_WAIT0()  asm volatile("cp.async.wait_group 0;")

__device__ __forceinline__ void mma_tf32(float* d, const unsigned* a, const unsigned* b) {
    asm volatile(
        "mma.sync.aligned.m16n8k8.row.col.f32.tf32.tf32.f32 "
        "{%0,%1,%2,%3}, {%4,%5,%6,%7}, {%8,%9}, {%0,%1,%2,%3};"
        : "+f"(d[0]), "+f"(d[1]), "+f"(d[2]), "+f"(d[3])
        : "r"(a[0]), "r"(a[1]), "r"(a[2]), "r"(a[3]), "r"(b[0]), "r"(b[1]));
}

// ---------------------------------------------------------------------------
// Prep: tf32-round x and the 6 weight matrices (once per launch)
// ---------------------------------------------------------------------------
__global__ void round_x_kernel(const float* __restrict__ in, float* __restrict__ out, int n4)
{
    int i = blockIdx.x * blockDim.x + threadIdx.x;
    if (i < n4) {
        float4 v = ((const float4*)in)[i];
        v.x = tf32_rna(v.x); v.y = tf32_rna(v.y);
        v.z = tf32_rna(v.z); v.w = tf32_rna(v.w);
        ((float4*)out)[i] = v;
    }
}

__global__ void round_w_kernel(const float* w0, const float* w1, const float* w2,
                               const float* w3, const float* w4, const float* w5,
                               float* __restrict__ out)
{
    const float* ws[6] = {w0, w1, w2, w3, w4, w5};
    const float* in = ws[blockIdx.y];
    float* o = out + blockIdx.y * (F * F);
    int i = blockIdx.x * blockDim.x + threadIdx.x;   // float4 index, 4096 per matrix
    float4 v = ((const float4*)in)[i];
    v.x = tf32_rna(v.x); v.y = tf32_rna(v.y);
    v.z = tf32_rna(v.z); v.w = tf32_rna(v.w);
    ((float4*)o)[i] = v;
}

// ---------------------------------------------------------------------------
// TF32 tensor-core GEMM:
//   C[M,128] = epi( A1 @ W1 (+ A2 @ W2) + bias )
// Block: 256 thr = 8 warps (2 row x 4 col), BM=64, BN=128, BK=32, cp.async
// double-buffered. Warp tile 32x32 via m16n8k8 (2 m-frags x 4 n-frags).
// Epilogues: (L2N? l2norm:nothing) -> relu -> (ROUND? tf32 round)
// ---------------------------------------------------------------------------
#define SA 36    // As row stride (floats): bank = 4g+tig, conflict-free
#define SB 132   // Bs row stride (floats): bank = 4tig+g, conflict-free
#define AS_BUF (64 * SA)
#define BS_BUF (32 * SB)
#define SMEM_BYTES ((2 * AS_BUF + 2 * BS_BUF) * 4)

template<bool TWO>
__device__ __forceinline__ void prefetch_tile(
    float* As, float* Bs,
    const float* A1, const float* W1, const float* A2, const float* W2,
    int t, int m0, int M, int tid)
{
    int buf = t & 1;
    const float* A = (TWO && t >= 4) ? A2 : A1;
    const float* W = (TWO && t >= 4) ? W2 : W1;
    int kk = (t & 3) * 32;
    // A tile: 64 x 32 floats = 512 float4, 2 per thread
#pragma unroll
    for (int i = 0; i < 2; i++) {
        int c  = tid + i * 256;
        int r  = c >> 3;
        int c4 = (c & 7) * 4;
        int m  = m0 + r;
        if (m < M)
            cp16(&As[buf * AS_BUF + r * SA + c4], A + (size_t)m * F + kk + c4);
    }
    // B tile: 32 x 128 floats = 1024 float4, 4 per thread
#pragma unroll
    for (int i = 0; i < 4; i++) {
        int c  = tid + i * 256;
        int k  = c >> 5;
        int n4 = (c & 31) * 4;
        cp16(&Bs[buf * BS_BUF + k * SB + n4], W + (size_t)(kk + k) * F + n4);
    }
    CP_COMMIT();
}

template<bool TWO, bool L2N, bool ROUND>
__global__ __launch_bounds__(256)
void gemm_tc_kernel(const float* __restrict__ A1, const float* __restrict__ W1,
                    const float* __restrict__ A2, const float* __restrict__ W2,
                    const float* __restrict__ bias, float* __restrict__ C, int M)
{
    extern __shared__ float sm[];
    float* As = sm;
    float* Bs = sm + 2 * AS_BUF;

    const int tid  = threadIdx.x;
    const int wid  = tid >> 5;
    const int lane = tid & 31;
    const int wr   = wid >> 2;        // 0..1
    const int wc   = wid & 3;         // 0..3
    const int g    = lane >> 2;       // 0..7
    const int tig  = lane & 3;        // 0..3
    const int m0   = blockIdx.x * 64;

    float acc[2][4][4];
#pragma unroll
    for (int mf = 0; mf < 2; mf++)
#pragma unroll
        for (int nf = 0; nf < 4; nf++)
#pragma unroll
            for (int q = 0; q < 4; q++) acc[mf][nf][q] = 0.0f;

    const int T = TWO ? 8 : 4;
    prefetch_tile<TWO>(As, Bs, A1, W1, A2, W2, 0, m0, M, tid);

    for (int t = 0; t < T; t++) {
        CP_WAIT0();
        __syncthreads();
        if (t + 1 < T)
            prefetch_tile<TWO>(As, Bs, A1, W1, A2, W2, t + 1, m0, M, tid);

        const float* as = &As[(t & 1) * AS_BUF];
        const float* bs = &Bs[(t & 1) * BS_BUF];

#pragma unroll
        for (int s = 0; s < 4; s++) {
            unsigned a[2][4], b[4][2];
#pragma unroll
            for (int mf = 0; mf < 2; mf++) {
                int row0 = wr * 32 + mf * 16 + g;
                a[mf][0] = __float_as_uint(as[row0 * SA + s * 8 + tig]);
                a[mf][1] = __float_as_uint(as[(row0 + 8) * SA + s * 8 + tig]);
                a[mf][2] = __float_as_uint(as[row0 * SA + s * 8 + tig + 4]);
                a[mf][3] = __float_as_uint(as[(row0 + 8) * SA + s * 8 + tig + 4]);
            }
#pragma unroll
            for (int nf = 0; nf < 4; nf++) {
                int col = wc * 32 + nf * 8 + g;
                b[nf][0] = __float_as_uint(bs[(s * 8 + tig) * SB + col]);
                b[nf][1] = __float_as_uint(bs[(s * 8 + tig + 4) * SB + col]);
            }
#pragma unroll
            for (int mf = 0; mf < 2; mf++)
#pragma unroll
                for (int nf = 0; nf < 4; nf++)
                    mma_tf32(acc[mf][nf], a[mf], b[nf]);
        }
    }

    // ---- epilogue ----
    // Per thread: rows r0 = wr*32+mf*16+g, r1 = r0+8; cols = wc*32+nf*8+2*tig+{0,1}
    float bv0[4], bv1[4];
#pragma unroll
    for (int nf = 0; nf < 4; nf++) {
        int cb = wc * 32 + nf * 8 + 2 * tig;
        bv0[nf] = bias[cb];
        bv1[nf] = bias[cb + 1];
    }
    // add bias in place
#pragma unroll
    for (int mf = 0; mf < 2; mf++)
#pragma unroll
        for (int nf = 0; nf < 4; nf++) {
            acc[mf][nf][0] += bv0[nf];
            acc[mf][nf][1] += bv1[nf];
            acc[mf][nf][2] += bv0[nf];
            acc[mf][nf][3] += bv1[nf];
        }

    float inv[2][2];   // [mf][row-half] inverse norm (or 1)
#pragma unroll
    for (int mf = 0; mf < 2; mf++) { inv[mf][0] = 1.f; inv[mf][1] = 1.f; }

    if (L2N) {
        __syncthreads();                     // done with mma smem
        float* rowsq = As;                   // reuse, 64 floats
        if (tid < 64) rowsq[tid] = 0.0f;
        __syncthreads();
#pragma unroll
        for (int mf = 0; mf < 2; mf++) {
#pragma unroll
            for (int half = 0; half < 2; half++) {
                float s = 0.f;
#pragma unroll
                for (int nf = 0; nf < 4; nf++) {
                    float v0 = acc[mf][nf][half * 2 + 0];
                    float v1 = acc[mf][nf][half * 2 + 1];
                    s = fmaf(v0, v0, fmaf(v1, v1, s));
                }
                // reduce over tig (4 consecutive lanes share g)
                s += __shfl_xor_sync(0xffffffffu, s, 1);
                s += __shfl_xor_sync(0xffffffffu, s, 2);
                if (tig == 0) {
                    int r = wr * 32 + mf * 16 + half * 8 + g;
                    atomicAdd(&rowsq[r], s);
                }
            }
        }
        __syncthreads();
#pragma unroll
        for (int mf = 0; mf < 2; mf++)
#pragma unroll
            for (int half = 0; half < 2; half++) {
                int r = wr * 32 + mf * 16 + half * 8 + g;
                inv[mf][half] = 1.0f / fmaxf(sqrtf(rowsq[r]), 1e-12f);
            }
    }

    // store
#pragma unroll
    for (int mf = 0; mf < 2; mf++) {
#pragma unroll
        for (int half = 0; half < 2; half++) {
            int m = m0 + wr * 32 + mf * 16 + half * 8 + g;
            if (m >= M) continue;
            float s = inv[mf][half];
#pragma unroll
            for (int nf = 0; nf < 4; nf++) {
                float v0 = fmaxf(acc[mf][nf][half * 2 + 0] * s, 0.f);
                float v1 = fmaxf(acc[mf][nf][half * 2 + 1] * s, 0.f);
                if (ROUND) { v0 = tf32_rna(v0); v1 = tf32_rna(v1); }
                float2 o = make_float2(v0, v1);
                *(float2*)(C + (size_t)m * F + wc * 32 + nf * 8 + 2 * tig) = o;
            }
        }
    }
}

// ---------------------------------------------------------------------------
// CSR-by-dst build
// ---------------------------------------------------------------------------
__global__ void hist_kernel(const int* __restrict__ dst, int* __restrict__ cnt, int E)
{
    int e = blockIdx.x * blockDim.x + threadIdx.x;
    if (e < E) atomicAdd(&cnt[dst[e]], 1);
}

#define SCAN_CHUNK 1024
__global__ void scan_block_kernel(const int* __restrict__ cnt, int* __restrict__ rowptr,
                                  int* __restrict__ blksum, int N)
{
    __shared__ int s[SCAN_CHUNK];
    int i = blockIdx.x * SCAN_CHUNK + threadIdx.x;
    int v = (i < N) ? cnt[i] : 0;
    s[threadIdx.x] = v;
    __syncthreads();
#pragma unroll
    for (int off = 1; off < SCAN_CHUNK; off <<= 1) {
        int t = (threadIdx.x >= off) ? s[threadIdx.x - off] : 0;
        __syncthreads();
        s[threadIdx.x] += t;
        __syncthreads();
    }
    if (i < N) rowptr[i] = s[threadIdx.x] - v;
    if (threadIdx.x == SCAN_CHUNK - 1) blksum[blockIdx.x] = s[threadIdx.x];
}

__global__ void scan_partials_kernel(int* blksum, int nb)
{
    if (threadIdx.x == 0 && blockIdx.x == 0) {
        int acc = 0;
        for (int i = 0; i < nb; i++) { int t = blksum[i]; blksum[i] = acc; acc += t; }
    }
}

__global__ void add_offsets_kernel(int* __restrict__ rowptr, int* __restrict__ cursor,
                                   const int* __restrict__ blksum, int N, int E)
{
    int i = blockIdx.x * blockDim.x + threadIdx.x;
    if (i < N) {
        int v = rowptr[i] + blksum[i >> 10];
        rowptr[i] = v;
        cursor[i] = v;
    }
    if (i == N) rowptr[N] = E;
}

__global__ void fill_csr_kernel(const int* __restrict__ src, const int* __restrict__ dst,
                                int* __restrict__ cursor, int* __restrict__ eidx, int E)
{
    int e = blockIdx.x * blockDim.x + threadIdx.x;
    if (e < E) {
        int pos = atomicAdd(&cursor[dst[e]], 1);
        eidx[pos] = src[e];
    }
}

// ---------------------------------------------------------------------------
// Gather-max: one warp per dst node, lane owns 4 contiguous features (float4)
// ---------------------------------------------------------------------------
__global__ void gather_max_kernel(const float* __restrict__ p,
                                  const int* __restrict__ rowptr,
                                  const int* __restrict__ eidx,
                                  float* __restrict__ agg, int N)
{
    int warp = (blockIdx.x * blockDim.x + threadIdx.x) >> 5;
    int lane = threadIdx.x & 31;
    if (warp >= N) return;
    int beg = __ldg(&rowptr[warp]);
    int end = __ldg(&rowptr[warp + 1]);

    float4 acc = make_float4(0.f, 0.f, 0.f, 0.f);
    int i = beg;
    for (; i + 3 < end; i += 4) {
        int s0 = __ldg(&eidx[i]);
        int s1 = __ldg(&eidx[i + 1]);
        int s2 = __ldg(&eidx[i + 2]);
        int s3 = __ldg(&eidx[i + 3]);
        float4 v0 = *(const float4*)(p + (size_t)s0 * F + lane * 4);
        float4 v1 = *(const float4*)(p + (size_t)s1 * F + lane * 4);
        float4 v2 = *(const float4*)(p + (size_t)s2 * F + lane * 4);
        float4 v3 = *(const float4*)(p + (size_t)s3 * F + lane * 4);
        acc.x = fmaxf(acc.x, fmaxf(fmaxf(v0.x, v1.x), fmaxf(v2.x, v3.x)));
        acc.y = fmaxf(acc.y, fmaxf(fmaxf(v0.y, v1.y), fmaxf(v2.y, v3.y)));
        acc.z = fmaxf(acc.z, fmaxf(fmaxf(v0.z, v1.z), fmaxf(v2.z, v3.z)));
        acc.w = fmaxf(acc.w, fmaxf(fmaxf(v0.w, v1.w), fmaxf(v2.w, v3.w)));
    }
    for (; i < end; i++) {
        int s = __ldg(&eidx[i]);
        float4 v = *(const float4*)(p + (size_t)s * F + lane * 4);
        acc.x = fmaxf(acc.x, v.x);
        acc.y = fmaxf(acc.y, v.y);
        acc.z = fmaxf(acc.z, v.z);
        acc.w = fmaxf(acc.w, v.w);
    }
    *(float4*)(agg + (size_t)warp * F + lane * 4) = acc;
}

// ---------------------------------------------------------------------------
extern "C" void kernel_launch(void* const* d_in, const int* in_sizes, int n_in,
                              void* d_out, int out_size)
{
    const float* x       = (const float*)d_in[0];
    const int*   src     = (const int*)  d_in[1];
    const int*   dst     = (const int*)  d_in[2];
    const float* W_pool1 = (const float*)d_in[3];
    const float* b_pool1 = (const float*)d_in[4];
    const float* W_self1 = (const float*)d_in[5];
    const float* W_neigh1= (const float*)d_in[6];
    const float* b1      = (const float*)d_in[7];
    const float* W_pool2 = (const float*)d_in[8];
    const float* b_pool2 = (const float*)d_in[9];
    const float* W_self2 = (const float*)d_in[10];
    const float* W_neigh2= (const float*)d_in[11];
    const float* b2      = (const float*)d_in[12];

    const int M = in_sizes[0] / F;       // 50000
    const int E = in_sizes[1];           // 1600000

    float *p, *agg, *h1, *xr, *w;
    int *cnt, *rowptr, *cursor, *eidx, *blksum;
    cudaGetSymbolAddress((void**)&p,      g_p);
    cudaGetSymbolAddress((void**)&agg,    g_agg);
    cudaGetSymbolAddress((void**)&h1,     g_h1);
    cudaGetSymbolAddress((void**)&xr,     g_xr);
    cudaGetSymbolAddress((void**)&w,      g_w);
    cudaGetSymbolAddress((void**)&cnt,    g_cnt);
    cudaGetSymbolAddress((void**)&rowptr, g_rowptr);
    cudaGetSymbolAddress((void**)&cursor, g_cursor);
    cudaGetSymbolAddress((void**)&eidx,   g_eidx);
    cudaGetSymbolAddress((void**)&blksum, g_blksum);
    float* out = (float*)d_out;

    const float* rWp1 = w + 0 * F * F;
    const float* rWs1 = w + 1 * F * F;
    const float* rWn1 = w + 2 * F * F;
    const float* rWp2 = w + 3 * F * F;
    const float* rWs2 = w + 4 * F * F;
    const float* rWn2 = w + 5 * F * F;

    // allow >48KB dynamic smem on the GEMM instantiations
    cudaFuncSetAttribute(gemm_tc_kernel<false, false, true>,
                         cudaFuncAttributeMaxDynamicSharedMemorySize, SMEM_BYTES);
    cudaFuncSetAttribute(gemm_tc_kernel<true, true, true>,
                         cudaFuncAttributeMaxDynamicSharedMemorySize, SMEM_BYTES);
    cudaFuncSetAttribute(gemm_tc_kernel<true, true, false>,
                         cudaFuncAttributeMaxDynamicSharedMemorySize, SMEM_BYTES);

    const int gblocks = (M + 63) / 64;
    const int eblocks = (E + 255) / 256;
    const int nb      = (M + SCAN_CHUNK - 1) / SCAN_CHUNK;
    const int wblocks = (M * 32 + 255) / 256;

    // ---- Prep: tf32-round inputs and weights ----
    round_x_kernel<<<(M * F / 4 + 255) / 256, 256>>>(x, xr, M * F / 4);
    round_w_kernel<<<dim3(16, 6), 256>>>(W_pool1, W_self1, W_neigh1,
                                         W_pool2, W_self2, W_neigh2, w);

    // ---- CSR build (once, serves both layers) ----
    cudaMemsetAsync(cnt, 0, (size_t)M * sizeof(int), 0);
    hist_kernel<<<eblocks, 256>>>(dst, cnt, E);
    scan_block_kernel<<<nb, SCAN_CHUNK>>>(cnt, rowptr, blksum, M);
    scan_partials_kernel<<<1, 32>>>(blksum, nb);
    add_offsets_kernel<<<(M + 256) / 256, 256>>>(rowptr, cursor, blksum, M, E);
    fill_csr_kernel<<<eblocks, 256>>>(src, dst, cursor, eidx, E);

    // ---- Layer 1 ----
    gemm_tc_kernel<false, false, true><<<gblocks, 256, SMEM_BYTES>>>(
        xr, rWp1, nullptr, nullptr, b_pool1, p, M);
    gather_max_kernel<<<wblocks, 256>>>(p, rowptr, eidx, agg, M);
    gemm_tc_kernel<true, true, true><<<gblocks, 256, SMEM_BYTES>>>(
        xr, rWs1, agg, rWn1, b1, h1, M);

    // ---- Layer 2 ----
    gemm_tc_kernel<false, false, true><<<gblocks, 256, SMEM_BYTES>>>(
        h1, rWp2, nullptr, nullptr, b_pool2, p, M);
    gather_max_kernel<<<wblocks, 256>>>(p, rowptr, eidx, agg, M);
    gemm_tc_kernel<true, true, false><<<gblocks, 256, SMEM_BYTES>>>(
        h1, rWs2, agg, rWn2, b2, out, M);
}

// round 4
// speedup vs baseline: 4.3523x; 1.0846x over previous
#include <cuda_runtime.h>
#include <cuda_fp16.h>
#include <cstdint>

// Problem constants (from reference setup_inputs)
#define NMAX 50048
#define EMAX 1600000
#define F 128

// Scratch (allocation-free rule: __device__ globals)
__device__ __align__(16) __half g_p[NMAX * F];   // relu(h @ W_pool + b_pool), fp16 (== tf32 mantissa)
__device__ __align__(16) float g_agg[NMAX * F];  // segment max (fp32, values fp16-representable)
__device__ __align__(16) float g_h1[NMAX * F];   // layer-1 output (full fp32)
__device__ __align__(16) float g_w[6 * F * F];   // tf32-rounded weights

// CSR-by-dst scratch
__device__ int g_cnt[NMAX];
__device__ int g_rowptr[NMAX + 1];
__device__ int g_cursor[NMAX];
__device__ int g_eidx[EMAX];
__device__ int g_blksum[64];

// ---------------------------------------------------------------------------
// Helpers
// ---------------------------------------------------------------------------
__device__ __forceinline__ unsigned tf32_rna_bits(float x) {
    unsigned u;
    asm("cvt.rna.tf32.f32 %0, %1;" : "=r"(u) : "f"(x));
    return u;
}
__device__ __forceinline__ float tf32_rna(float x) {
    return __uint_as_float(tf32_rna_bits(x));
}

__device__ __forceinline__ void cp16(void* smem_dst, const void* gsrc) {
    unsigned d = (unsigned)__cvta_generic_to_shared(smem_dst);
    asm volatile("cp.async.cg.shared.global [%0], [%1], 16;" :: "r"(d), "l"(gsrc));
}
#define CP_COMMIT() asm volatile("cp.async.commit_group;")
#define CP_WAIT0()  asm volatile("cp.async.wait_group 0;")

__device__ __forceinline__ void mma_tf32(float* d, const unsigned* a, const unsigned* b) {
    asm volatile(
        "mma.sync.aligned.m16n8k8.row.col.f32.tf32.tf32.f32 "
        "{%0,%1,%2,%3}, {%4,%5,%6,%7}, {%8,%9}, {%0,%1,%2,%3};"
        : "+f"(d[0]), "+f"(d[1]), "+f"(d[2]), "+f"(d[3])
        : "r"(a[0]), "r"(a[1]), "r"(a[2]), "r"(a[3]), "r"(b[0]), "r"(b[1]));
}

// ---------------------------------------------------------------------------
// Prep: tf32-round the 6 weight matrices (once per launch, ~2us)
// ---------------------------------------------------------------------------
__global__ void round_w_kernel(const float* w0, const float* w1, const float* w2,
                               const float* w3, const float* w4, const float* w5,
                               float* __restrict__ out)
{
    const float* ws[6] = {w0, w1, w2, w3, w4, w5};
    const float* in = ws[blockIdx.y];
    float* o = out + blockIdx.y * (F * F);
    int i = blockIdx.x * blockDim.x + threadIdx.x;   // float4 index, 4096 per matrix
    float4 v = ((const float4*)in)[i];
    v.x = tf32_rna(v.x); v.y = tf32_rna(v.y);
    v.z = tf32_rna(v.z); v.w = tf32_rna(v.w);
    ((float4*)o)[i] = v;
}

// ---------------------------------------------------------------------------
// TF32 tensor-core GEMM:
//   C[M,128] = epi( A1 @ W1 (+ A2 @ W2) + bias )
// A-fragments are tf32-rounded (RNA) in-register at LDS time, so A inputs may
// be raw fp32. Weights must be pre-rounded.
// Block: 256 thr = 8 warps (2 row x 4 col), BM=64, BN=128, BK=32, cp.async
// double-buffered. Warp tile 32x32 via m16n8k8 (2 m-frags x 4 n-frags).
// Epilogues: (L2N? rowwise l2norm) -> relu -> store (HALFOUT? fp16 : fp32)
// ---------------------------------------------------------------------------
#define SA 36    // As row stride (floats): conflict-free fragment loads
#define SB 132   // Bs row stride (floats): conflict-free fragment loads
#define AS_BUF (64 * SA)
#define BS_BUF (32 * SB)
#define SMEM_BYTES ((2 * AS_BUF + 2 * BS_BUF) * 4)

template<bool TWO>
__device__ __forceinline__ void prefetch_tile(
    float* As, float* Bs,
    const float* A1, const float* W1, const float* A2, const float* W2,
    int t, int m0, int M, int tid)
{
    int buf = t & 1;
    const float* A = (TWO && t >= 4) ? A2 : A1;
    const float* W = (TWO && t >= 4) ? W2 : W1;
    int kk = (t & 3) * 32;
    // A tile: 64 x 32 floats = 512 float4, 2 per thread
#pragma unroll
    for (int i = 0; i < 2; i++) {
        int c  = tid + i * 256;
        int r  = c >> 3;
        int c4 = (c & 7) * 4;
        int m  = m0 + r;
        if (m < M)
            cp16(&As[buf * AS_BUF + r * SA + c4], A + (size_t)m * F + kk + c4);
    }
    // B tile: 32 x 128 floats = 1024 float4, 4 per thread
#pragma unroll
    for (int i = 0; i < 4; i++) {
        int c  = tid + i * 256;
        int k  = c >> 5;
        int n4 = (c & 31) * 4;
        cp16(&Bs[buf * BS_BUF + k * SB + n4], W + (size_t)(kk + k) * F + n4);
    }
    CP_COMMIT();
}

template<bool TWO, bool L2N, bool HALFOUT>
__global__ __launch_bounds__(256)
void gemm_tc_kernel(const float* __restrict__ A1, const float* __restrict__ W1,
                    const float* __restrict__ A2, const float* __restrict__ W2,
                    const float* __restrict__ bias, void* __restrict__ Cout, int M)
{
    extern __shared__ float sm[];
    float* As = sm;
    float* Bs = sm + 2 * AS_BUF;

    const int tid  = threadIdx.x;
    const int wid  = tid >> 5;
    const int lane = tid & 31;
    const int wr   = wid >> 2;        // 0..1
    const int wc   = wid & 3;         // 0..3
    const int g    = lane >> 2;       // 0..7
    const int tig  = lane & 3;        // 0..3
    const int m0   = blockIdx.x * 64;

    float acc[2][4][4];
#pragma unroll
    for (int mf = 0; mf < 2; mf++)
#pragma unroll
        for (int nf = 0; nf < 4; nf++)
#pragma unroll
            for (int q = 0; q < 4; q++) acc[mf][nf][q] = 0.0f;

    const int T = TWO ? 8 : 4;
    prefetch_tile<TWO>(As, Bs, A1, W1, A2, W2, 0, m0, M, tid);

    for (int t = 0; t < T; t++) {
        CP_WAIT0();
        __syncthreads();
        if (t + 1 < T)
            prefetch_tile<TWO>(As, Bs, A1, W1, A2, W2, t + 1, m0, M, tid);

        const float* as = &As[(t & 1) * AS_BUF];
        const float* bs = &Bs[(t & 1) * BS_BUF];

#pragma unroll
        for (int s = 0; s < 4; s++) {
            unsigned a[2][4], b[4][2];
#pragma unroll
            for (int mf = 0; mf < 2; mf++) {
                int row0 = wr * 32 + mf * 16 + g;
                a[mf][0] = tf32_rna_bits(as[row0 * SA + s * 8 + tig]);
                a[mf][1] = tf32_rna_bits(as[(row0 + 8) * SA + s * 8 + tig]);
                a[mf][2] = tf32_rna_bits(as[row0 * SA + s * 8 + tig + 4]);
                a[mf][3] = tf32_rna_bits(as[(row0 + 8) * SA + s * 8 + tig + 4]);
            }
#pragma unroll
            for (int nf = 0; nf < 4; nf++) {
                int col = wc * 32 + nf * 8 + g;
                b[nf][0] = __float_as_uint(bs[(s * 8 + tig) * SB + col]);
                b[nf][1] = __float_as_uint(bs[(s * 8 + tig + 4) * SB + col]);
            }
#pragma unroll
            for (int mf = 0; mf < 2; mf++)
#pragma unroll
                for (int nf = 0; nf < 4; nf++)
                    mma_tf32(acc[mf][nf], a[mf], b[nf]);
        }
    }

    // ---- epilogue ----
    float bv0[4], bv1[4];
#pragma unroll
    for (int nf = 0; nf < 4; nf++) {
        int cb = wc * 32 + nf * 8 + 2 * tig;
        bv0[nf] = bias[cb];
        bv1[nf] = bias[cb + 1];
    }
#pragma unroll
    for (int mf = 0; mf < 2; mf++)
#pragma unroll
        for (int nf = 0; nf < 4; nf++) {
            acc[mf][nf][0] += bv0[nf];
            acc[mf][nf][1] += bv1[nf];
            acc[mf][nf][2] += bv0[nf];
            acc[mf][nf][3] += bv1[nf];
        }

    float inv[2][2];
#pragma unroll
    for (int mf = 0; mf < 2; mf++) { inv[mf][0] = 1.f; inv[mf][1] = 1.f; }

    if (L2N) {
        __syncthreads();
        float* rowsq = As;                   // reuse, 64 floats
        if (tid < 64) rowsq[tid] = 0.0f;
        __syncthreads();
#pragma unroll
        for (int mf = 0; mf < 2; mf++) {
#pragma unroll
            for (int half = 0; half < 2; half++) {
                float s = 0.f;
#pragma unroll
                for (int nf = 0; nf < 4; nf++) {
                    float v0 = acc[mf][nf][half * 2 + 0];
                    float v1 = acc[mf][nf][half * 2 + 1];
                    s = fmaf(v0, v0, fmaf(v1, v1, s));
                }
                s += __shfl_xor_sync(0xffffffffu, s, 1);
                s += __shfl_xor_sync(0xffffffffu, s, 2);
                if (tig == 0) {
                    int r = wr * 32 + mf * 16 + half * 8 + g;
                    atomicAdd(&rowsq[r], s);
                }
            }
        }
        __syncthreads();
#pragma unroll
        for (int mf = 0; mf < 2; mf++)
#pragma unroll
            for (int half = 0; half < 2; half++) {
                int r = wr * 32 + mf * 16 + half * 8 + g;
                inv[mf][half] = 1.0f / fmaxf(sqrtf(rowsq[r]), 1e-12f);
            }
    }

    // store (relu; fp16 or fp32)
#pragma unroll
    for (int mf = 0; mf < 2; mf++) {
#pragma unroll
        for (int half = 0; half < 2; half++) {
            int m = m0 + wr * 32 + mf * 16 + half * 8 + g;
            if (m >= M) continue;
            float s = inv[mf][half];
#pragma unroll
            for (int nf = 0; nf < 4; nf++) {
                float v0 = fmaxf(acc[mf][nf][half * 2 + 0] * s, 0.f);
                float v1 = fmaxf(acc[mf][nf][half * 2 + 1] * s, 0.f);
                int col = wc * 32 + nf * 8 + 2 * tig;
                if (HALFOUT) {
                    __half2 hv = __floats2half2_rn(v0, v1);
                    *(__half2*)((__half*)Cout + (size_t)m * F + col) = hv;
                } else {
                    *(float2*)((float*)Cout + (size_t)m * F + col) = make_float2(v0, v1);
                }
            }
        }
    }
}

// ---------------------------------------------------------------------------
// CSR-by-dst build
// ---------------------------------------------------------------------------
__global__ void hist_kernel(const int* __restrict__ dst, int* __restrict__ cnt, int E)
{
    int e = blockIdx.x * blockDim.x + threadIdx.x;
    if (e < E) atomicAdd(&cnt[dst[e]], 1);
}

#define SCAN_CHUNK 1024
__global__ void scan_block_kernel(const int* __restrict__ cnt, int* __restrict__ rowptr,
                                  int* __restrict__ blksum, int N)
{
    __shared__ int s[SCAN_CHUNK];
    int i = blockIdx.x * SCAN_CHUNK + threadIdx.x;
    int v = (i < N) ? cnt[i] : 0;
    s[threadIdx.x] = v;
    __syncthreads();
#pragma unroll
    for (int off = 1; off < SCAN_CHUNK; off <<= 1) {
        int t = (threadIdx.x >= off) ? s[threadIdx.x - off] : 0;
        __syncthreads();
        s[threadIdx.x] += t;
        __syncthreads();
    }
    if (i < N) rowptr[i] = s[threadIdx.x] - v;
    if (threadIdx.x == SCAN_CHUNK - 1) blksum[blockIdx.x] = s[threadIdx.x];
}

__global__ void scan_partials_kernel(int* blksum, int nb)
{
    if (threadIdx.x == 0 && blockIdx.x == 0) {
        int acc = 0;
        for (int i = 0; i < nb; i++) { int t = blksum[i]; blksum[i] = acc; acc += t; }
    }
}

__global__ void add_offsets_kernel(int* __restrict__ rowptr, int* __restrict__ cursor,
                                   const int* __restrict__ blksum, int N, int E)
{
    int i = blockIdx.x * blockDim.x + threadIdx.x;
    if (i < N) {
        int v = rowptr[i] + blksum[i >> 10];
        rowptr[i] = v;
        cursor[i] = v;
    }
    if (i == N) rowptr[N] = E;
}

__global__ void fill_csr_kernel(const int* __restrict__ src, const int* __restrict__ dst,
                                int* __restrict__ cursor, int* __restrict__ eidx, int E)
{
    int e = blockIdx.x * blockDim.x + threadIdx.x;
    if (e < E) {
        int pos = atomicAdd(&cursor[dst[e]], 1);
        eidx[pos] = src[e];
    }
}

// ---------------------------------------------------------------------------
// Gather-max over fp16 rows: one warp per dst node, lane owns 4 halfs (8B).
// max(round(v)) == round(max(v)) (monotone rounding), so fp16 p is exact
// w.r.t. tf32-rounded semantics. Output agg in fp32 (conversion exact).
// ---------------------------------------------------------------------------
__global__ void gather_max_kernel(const __half2* __restrict__ p2,
                                  const int* __restrict__ rowptr,
                                  const int* __restrict__ eidx,
                                  float* __restrict__ agg, int N)
{
    int warp = (blockIdx.x * blockDim.x + threadIdx.x) >> 5;
    int lane = threadIdx.x & 31;
    if (warp >= N) return;
    int beg = __ldg(&rowptr[warp]);
    int end = __ldg(&rowptr[warp + 1]);

    __half2 z = __float2half2_rn(0.f);
    __half2 a0 = z, a1 = z;
    int i = beg;
    for (; i + 3 < end; i += 4) {
        int s0 = __ldg(&eidx[i]);
        int s1 = __ldg(&eidx[i + 1]);
        int s2 = __ldg(&eidx[i + 2]);
        int s3 = __ldg(&eidx[i + 3]);
        const __half2* r0 = p2 + (size_t)s0 * 64 + lane * 2;
        const __half2* r1 = p2 + (size_t)s1 * 64 + lane * 2;
        const __half2* r2 = p2 + (size_t)s2 * 64 + lane * 2;
        const __half2* r3 = p2 + (size_t)s3 * 64 + lane * 2;
        __half2 v00 = r0[0], v01 = r0[1];
        __half2 v10 = r1[0], v11 = r1[1];
        __half2 v20 = r2[0], v21 = r2[1];
        __half2 v30 = r3[0], v31 = r3[1];
        a0 = __hmax2(a0, __hmax2(__hmax2(v00, v10), __hmax2(v20, v30)));
        a1 = __hmax2(a1, __hmax2(__hmax2(v01, v11), __hmax2(v21, v31)));
    }
    for (; i < end; i++) {
        int s = __ldg(&eidx[i]);
        const __half2* r = p2 + (size_t)s * 64 + lane * 2;
        a0 = __hmax2(a0, r[0]);
        a1 = __hmax2(a1, r[1]);
    }
    float2 f0 = __half22float2(a0);
    float2 f1 = __half22float2(a1);
    *(float4*)(agg + (size_t)warp * F + lane * 4) = make_float4(f0.x, f0.y, f1.x, f1.y);
}

// ---------------------------------------------------------------------------
extern "C" void kernel_launch(void* const* d_in, const int* in_sizes, int n_in,
                              void* d_out, int out_size)
{
    const float* x       = (const float*)d_in[0];
    const int*   src     = (const int*)  d_in[1];
    const int*   dst     = (const int*)  d_in[2];
    const float* W_pool1 = (const float*)d_in[3];
    const float* b_pool1 = (const float*)d_in[4];
    const float* W_self1 = (const float*)d_in[5];
    const float* W_neigh1= (const float*)d_in[6];
    const float* b1      = (const float*)d_in[7];
    const float* W_pool2 = (const float*)d_in[8];
    const float* b_pool2 = (const float*)d_in[9];
    const float* W_self2 = (const float*)d_in[10];
    const float* W_neigh2= (const float*)d_in[11];
    const float* b2      = (const float*)d_in[12];

    const int M = in_sizes[0] / F;       // 50000
    const int E = in_sizes[1];           // 1600000

    __half* p;
    float *agg, *h1, *w;
    int *cnt, *rowptr, *cursor, *eidx, *blksum;
    cudaGetSymbolAddress((void**)&p,      g_p);
    cudaGetSymbolAddress((void**)&agg,    g_agg);
    cudaGetSymbolAddress((void**)&h1,     g_h1);
    cudaGetSymbolAddress((void**)&w,      g_w);
    cudaGetSymbolAddress((void**)&cnt,    g_cnt);
    cudaGetSymbolAddress((void**)&rowptr, g_rowptr);
    cudaGetSymbolAddress((void**)&cursor, g_cursor);
    cudaGetSymbolAddress((void**)&eidx,   g_eidx);
    cudaGetSymbolAddress((void**)&blksum, g_blksum);
    float* out = (float*)d_out;

    const float* rWp1 = w + 0 * F * F;
    const float* rWs1 = w + 1 * F * F;
    const float* rWn1 = w + 2 * F * F;
    const float* rWp2 = w + 3 * F * F;
    const float* rWs2 = w + 4 * F * F;
    const float* rWn2 = w + 5 * F * F;

    cudaFuncSetAttribute(gemm_tc_kernel<false, false, true>,
                         cudaFuncAttributeMaxDynamicSharedMemorySize, SMEM_BYTES);
    cudaFuncSetAttribute(gemm_tc_kernel<true, true, false>,
                         cudaFuncAttributeMaxDynamicSharedMemorySize, SMEM_BYTES);

    const int gblocks = (M + 63) / 64;
    const int eblocks = (E + 255) / 256;
    const int nb      = (M + SCAN_CHUNK - 1) / SCAN_CHUNK;
    const int wblocks = (M * 32 + 255) / 256;

    // Order chosen so ncu (-s 5) captures the pool GEMM (5th launch).
    round_w_kernel<<<dim3(16, 6), 256>>>(W_pool1, W_self1, W_neigh1,
                                         W_pool2, W_self2, W_neigh2, w);     // 1
    cudaMemsetAsync(cnt, 0, (size_t)M * sizeof(int), 0);                     // 2
    hist_kernel<<<eblocks, 256>>>(dst, cnt, E);                              // 3
    scan_block_kernel<<<nb, SCAN_CHUNK>>>(cnt, rowptr, blksum, M);           // 4
    gemm_tc_kernel<false, false, true><<<gblocks, 256, SMEM_BYTES>>>(        // 5: pool GEMM L1
        x, rWp1, nullptr, nullptr, b_pool1, p, M);
    scan_partials_kernel<<<1, 32>>>(blksum, nb);                             // 6
    add_offsets_kernel<<<(M + 256) / 256, 256>>>(rowptr, cursor, blksum, M, E); // 7
    fill_csr_kernel<<<eblocks, 256>>>(src, dst, cursor, eidx, E);            // 8

    // ---- Layer 1 (cont.) ----
    gather_max_kernel<<<wblocks, 256>>>((const __half2*)p, rowptr, eidx, agg, M);
    gemm_tc_kernel<true, true, false><<<gblocks, 256, SMEM_BYTES>>>(
        x, rWs1, agg, rWn1, b1, h1, M);

    // ---- Layer 2 ----
    gemm_tc_kernel<false, false, true><<<gblocks, 256, SMEM_BYTES>>>(
        h1, rWp2, nullptr, nullptr, b_pool2, p, M);
    gather_max_kernel<<<wblocks, 256>>>((const __half2*)p, rowptr, eidx, agg, M);
    gemm_tc_kernel<true, true, false><<<gblocks, 256, SMEM_BYTES>>>(
        h1, rWs2, agg, rWn2, b2, out, M);
}

// round 5
// speedup vs baseline: 4.3639x; 1.0027x over previous
#include <cuda_runtime.h>
#include <cuda_fp16.h>
#include <cstdint>

// Problem constants (from reference setup_inputs)
#define NMAX 50048
#define EMAX 1600000
#define F 128

// Scratch (allocation-free rule: __device__ globals)
__device__ __align__(16) __half g_p[NMAX * F];   // relu(h @ W_pool + b_pool), fp16
__device__ __align__(16) float g_agg[NMAX * F];  // segment max (fp32, fp16-grid values)
__device__ __align__(16) float g_h1[NMAX * F];   // layer-1 output (tf32-rounded)
__device__ __align__(16) float g_xr[NMAX * F];   // tf32-rounded x
__device__ __align__(16) float g_w[6 * F * F];   // tf32-rounded weights

// CSR-by-dst scratch
__device__ int g_cnt[NMAX];
__device__ int g_rowptr[NMAX + 1];
__device__ int g_cursor[NMAX];
__device__ int g_eidx[EMAX];
__device__ int g_blksum[64];

// ---------------------------------------------------------------------------
// Helpers
// ---------------------------------------------------------------------------
__device__ __forceinline__ float tf32_rna(float x) {
    unsigned u;
    asm("cvt.rna.tf32.f32 %0, %1;" : "=r"(u) : "f"(x));
    return __uint_as_float(u);
}

__device__ __forceinline__ void cp16(void* smem_dst, const void* gsrc) {
    unsigned d = (unsigned)__cvta_generic_to_shared(smem_dst);
    asm volatile("cp.async.cg.shared.global [%0], [%1], 16;" :: "r"(d), "l"(gsrc));
}
#define CP_COMMIT() asm volatile("cp.async.commit_group;")
#define CP_WAIT0()  asm volatile("cp.async.wait_group 0;")

__device__ __forceinline__ void mma_tf32(float* d, const unsigned* a, const unsigned* b) {
    asm volatile(
        "mma.sync.aligned.m16n8k8.row.col.f32.tf32.tf32.f32 "
        "{%0,%1,%2,%3}, {%4,%5,%6,%7}, {%8,%9}, {%0,%1,%2,%3};"
        : "+f"(d[0]), "+f"(d[1]), "+f"(d[2]), "+f"(d[3])
        : "r"(a[0]), "r"(a[1]), "r"(a[2]), "r"(a[3]), "r"(b[0]), "r"(b[1]));
}

// ldmatrix.x4 on b16 lanes: loads a full m16k8 tf32 A-fragment in one op.
__device__ __forceinline__ void ldsm_x4(unsigned* a, unsigned saddr) {
    asm volatile("ldmatrix.sync.aligned.m8n8.x4.shared.b16 {%0,%1,%2,%3}, [%4];"
        : "=r"(a[0]), "=r"(a[1]), "=r"(a[2]), "=r"(a[3]) : "r"(saddr));
}

// ---------------------------------------------------------------------------
// Prep kernels: tf32-round x and the 6 weight matrices (once per launch)
// ---------------------------------------------------------------------------
__global__ void round_x_kernel(const float* __restrict__ in, float* __restrict__ out, int n4)
{
    int i = blockIdx.x * blockDim.x + threadIdx.x;
    if (i < n4) {
        float4 v = ((const float4*)in)[i];
        v.x = tf32_rna(v.x); v.y = tf32_rna(v.y);
        v.z = tf32_rna(v.z); v.w = tf32_rna(v.w);
        ((float4*)out)[i] = v;
    }
}

__global__ void round_w_kernel(const float* w0, const float* w1, const float* w2,
                               const float* w3, const float* w4, const float* w5,
                               float* __restrict__ out)
{
    const float* ws[6] = {w0, w1, w2, w3, w4, w5};
    const float* in = ws[blockIdx.y];
    float* o = out + blockIdx.y * (F * F);
    int i = blockIdx.x * blockDim.x + threadIdx.x;
    float4 v = ((const float4*)in)[i];
    v.x = tf32_rna(v.x); v.y = tf32_rna(v.y);
    v.z = tf32_rna(v.z); v.w = tf32_rna(v.w);
    ((float4*)o)[i] = v;
}

// ---------------------------------------------------------------------------
// TF32 tensor-core GEMM:  C[M,128] = epi( A1 @ W1 (+ A2 @ W2) + bias )
// All A inputs and weights must already be on the tf32 grid.
// Block: 256 thr = 8 warps (2x4), BM=64, BN=128, BK=32, cp.async dbl-buffered.
// A-fragments loaded with ldmatrix.x4 (conflict-free via SA=36 padding).
// Epilogues: (L2N? rowwise l2norm) -> relu -> (ROUND? tf32) -> fp16/fp32 store
// ---------------------------------------------------------------------------
#define SA 36    // As row stride (floats)
#define SB 132   // Bs row stride (floats)
#define AS_BUF (64 * SA)
#define BS_BUF (32 * SB)
#define SMEM_BYTES ((2 * AS_BUF + 2 * BS_BUF) * 4)

template<bool TWO>
__device__ __forceinline__ void prefetch_tile(
    float* As, float* Bs,
    const float* A1, const float* W1, const float* A2, const float* W2,
    int t, int m0, int M, int tid)
{
    int buf = t & 1;
    const float* A = (TWO && t >= 4) ? A2 : A1;
    const float* W = (TWO && t >= 4) ? W2 : W1;
    int kk = (t & 3) * 32;
#pragma unroll
    for (int i = 0; i < 2; i++) {
        int c  = tid + i * 256;
        int r  = c >> 3;
        int c4 = (c & 7) * 4;
        int m  = m0 + r;
        if (m < M)
            cp16(&As[buf * AS_BUF + r * SA + c4], A + (size_t)m * F + kk + c4);
    }
#pragma unroll
    for (int i = 0; i < 4; i++) {
        int c  = tid + i * 256;
        int k  = c >> 5;
        int n4 = (c & 31) * 4;
        cp16(&Bs[buf * BS_BUF + k * SB + n4], W + (size_t)(kk + k) * F + n4);
    }
    CP_COMMIT();
}

template<bool TWO, bool L2N, bool HALFOUT, bool ROUND>
__global__ __launch_bounds__(256)
void gemm_tc_kernel(const float* __restrict__ A1, const float* __restrict__ W1,
                    const float* __restrict__ A2, const float* __restrict__ W2,
                    const float* __restrict__ bias, void* __restrict__ Cout, int M)
{
    extern __shared__ float sm[];
    float* As = sm;
    float* Bs = sm + 2 * AS_BUF;

    const int tid  = threadIdx.x;
    const int wid  = tid >> 5;
    const int lane = tid & 31;
    const int wr   = wid >> 2;        // 0..1
    const int wc   = wid & 3;         // 0..3
    const int g    = lane >> 2;       // 0..7
    const int tig  = lane & 3;        // 0..3
    const int m0   = blockIdx.x * 64;

    // ldmatrix per-lane row addresses (bytes, shared space), per mf
    unsigned as_u32 = (unsigned)__cvta_generic_to_shared(As);
    const int lrow  = lane & 15;
    const int kadd  = (lane & 16) ? 4 : 0;
    unsigned aaddr[2];
#pragma unroll
    for (int mf = 0; mf < 2; mf++)
        aaddr[mf] = as_u32 + ((wr * 32 + mf * 16 + lrow) * SA + kadd) * 4;

    float acc[2][4][4];
#pragma unroll
    for (int mf = 0; mf < 2; mf++)
#pragma unroll
        for (int nf = 0; nf < 4; nf++)
#pragma unroll
            for (int q = 0; q < 4; q++) acc[mf][nf][q] = 0.0f;

    const int T = TWO ? 8 : 4;
    prefetch_tile<TWO>(As, Bs, A1, W1, A2, W2, 0, m0, M, tid);

    for (int t = 0; t < T; t++) {
        CP_WAIT0();
        __syncthreads();
        if (t + 1 < T)
            prefetch_tile<TWO>(As, Bs, A1, W1, A2, W2, t + 1, m0, M, tid);

        const unsigned abase = (t & 1) * (AS_BUF * 4);
        const float* bs = &Bs[(t & 1) * BS_BUF];

#pragma unroll
        for (int s = 0; s < 4; s++) {
            unsigned a[2][4], b[4][2];
#pragma unroll
            for (int mf = 0; mf < 2; mf++)
                ldsm_x4(a[mf], aaddr[mf] + abase + s * 32);
#pragma unroll
            for (int nf = 0; nf < 4; nf++) {
                int col = wc * 32 + nf * 8 + g;
                b[nf][0] = __float_as_uint(bs[(s * 8 + tig) * SB + col]);
                b[nf][1] = __float_as_uint(bs[(s * 8 + tig + 4) * SB + col]);
            }
#pragma unroll
            for (int mf = 0; mf < 2; mf++)
#pragma unroll
                for (int nf = 0; nf < 4; nf++)
                    mma_tf32(acc[mf][nf], a[mf], b[nf]);
        }
    }

    // ---- epilogue ----
    float bv0[4], bv1[4];
#pragma unroll
    for (int nf = 0; nf < 4; nf++) {
        int cb = wc * 32 + nf * 8 + 2 * tig;
        bv0[nf] = bias[cb];
        bv1[nf] = bias[cb + 1];
    }
#pragma unroll
    for (int mf = 0; mf < 2; mf++)
#pragma unroll
        for (int nf = 0; nf < 4; nf++) {
            acc[mf][nf][0] += bv0[nf];
            acc[mf][nf][1] += bv1[nf];
            acc[mf][nf][2] += bv0[nf];
            acc[mf][nf][3] += bv1[nf];
        }

    float inv[2][2];
#pragma unroll
    for (int mf = 0; mf < 2; mf++) { inv[mf][0] = 1.f; inv[mf][1] = 1.f; }

    if (L2N) {
        __syncthreads();
        float* rowsq = As;                   // reuse, 64 floats
        if (tid < 64) rowsq[tid] = 0.0f;
        __syncthreads();
#pragma unroll
        for (int mf = 0; mf < 2; mf++) {
#pragma unroll
            for (int half = 0; half < 2; half++) {
                float s = 0.f;
#pragma unroll
                for (int nf = 0; nf < 4; nf++) {
                    float v0 = acc[mf][nf][half * 2 + 0];
                    float v1 = acc[mf][nf][half * 2 + 1];
                    s = fmaf(v0, v0, fmaf(v1, v1, s));
                }
                s += __shfl_xor_sync(0xffffffffu, s, 1);
                s += __shfl_xor_sync(0xffffffffu, s, 2);
                if (tig == 0) {
                    int r = wr * 32 + mf * 16 + half * 8 + g;
                    atomicAdd(&rowsq[r], s);
                }
            }
        }
        __syncthreads();
#pragma unroll
        for (int mf = 0; mf < 2; mf++)
#pragma unroll
            for (int half = 0; half < 2; half++) {
                int r = wr * 32 + mf * 16 + half * 8 + g;
                inv[mf][half] = 1.0f / fmaxf(sqrtf(rowsq[r]), 1e-12f);
            }
    }

    // store
#pragma unroll
    for (int mf = 0; mf < 2; mf++) {
#pragma unroll
        for (int half = 0; half < 2; half++) {
            int m = m0 + wr * 32 + mf * 16 + half * 8 + g;
            if (m >= M) continue;
            float s = inv[mf][half];
#pragma unroll
            for (int nf = 0; nf < 4; nf++) {
                float v0 = fmaxf(acc[mf][nf][half * 2 + 0] * s, 0.f);
                float v1 = fmaxf(acc[mf][nf][half * 2 + 1] * s, 0.f);
                int col = wc * 32 + nf * 8 + 2 * tig;
                if (HALFOUT) {
                    __half2 hv = __floats2half2_rn(v0, v1);
                    *(__half2*)((__half*)Cout + (size_t)m * F + col) = hv;
                } else {
                    if (ROUND) { v0 = tf32_rna(v0); v1 = tf32_rna(v1); }
                    *(float2*)((float*)Cout + (size_t)m * F + col) = make_float2(v0, v1);
                }
            }
        }
    }
}

// ---------------------------------------------------------------------------
// CSR-by-dst build
// ---------------------------------------------------------------------------
__global__ void hist_kernel(const int* __restrict__ dst, int* __restrict__ cnt, int E)
{
    int e = blockIdx.x * blockDim.x + threadIdx.x;
    if (e < E) atomicAdd(&cnt[dst[e]], 1);
}

#define SCAN_CHUNK 1024
__global__ void scan_block_kernel(const int* __restrict__ cnt, int* __restrict__ rowptr,
                                  int* __restrict__ blksum, int N)
{
    __shared__ int s[SCAN_CHUNK];
    int i = blockIdx.x * SCAN_CHUNK + threadIdx.x;
    int v = (i < N) ? cnt[i] : 0;
    s[threadIdx.x] = v;
    __syncthreads();
#pragma unroll
    for (int off = 1; off < SCAN_CHUNK; off <<= 1) {
        int t = (threadIdx.x >= off) ? s[threadIdx.x - off] : 0;
        __syncthreads();
        s[threadIdx.x] += t;
        __syncthreads();
    }
    if (i < N) rowptr[i] = s[threadIdx.x] - v;
    if (threadIdx.x == SCAN_CHUNK - 1) blksum[blockIdx.x] = s[threadIdx.x];
}

// single-warp shfl scan over <=64 partials (nb = 49)
__global__ void scan_partials_kernel(int* blksum, int nb)
{
    int lane = threadIdx.x & 31;
    int v0 = (lane < nb) ? blksum[lane] : 0;
    int v1 = (lane + 32 < nb) ? blksum[lane + 32] : 0;
    int s0 = v0, s1 = v1;
#pragma unroll
    for (int o = 1; o < 32; o <<= 1) {
        int t0 = __shfl_up_sync(0xffffffffu, s0, o);
        int t1 = __shfl_up_sync(0xffffffffu, s1, o);
        if (lane >= o) { s0 += t0; s1 += t1; }
    }
    int tot0 = __shfl_sync(0xffffffffu, s0, 31);
    s1 += tot0;
    if (lane < nb) blksum[lane] = s0 - v0;
    if (lane + 32 < nb) blksum[lane + 32] = s1 - v1;
}

__global__ void add_offsets_kernel(int* __restrict__ rowptr, int* __restrict__ cursor,
                                   const int* __restrict__ blksum, int N, int E)
{
    int i = blockIdx.x * blockDim.x + threadIdx.x;
    if (i < N) {
        int v = rowptr[i] + blksum[i >> 10];
        rowptr[i] = v;
        cursor[i] = v;
    }
    if (i == N) rowptr[N] = E;
}

__global__ void fill_csr_kernel(const int* __restrict__ src, const int* __restrict__ dst,
                                int* __restrict__ cursor, int* __restrict__ eidx, int E)
{
    int e = blockIdx.x * blockDim.x + threadIdx.x;
    if (e < E) {
        int pos = atomicAdd(&cursor[dst[e]], 1);
        eidx[pos] = src[e];
    }
}

// ---------------------------------------------------------------------------
// Gather-max over fp16 rows: one warp per dst node, lane owns 4 halfs (8B)
// ---------------------------------------------------------------------------
__global__ void gather_max_kernel(const __half2* __restrict__ p2,
                                  const int* __restrict__ rowptr,
                                  const int* __restrict__ eidx,
                                  float* __restrict__ agg, int N)
{
    int warp = (blockIdx.x * blockDim.x + threadIdx.x) >> 5;
    int lane = threadIdx.x & 31;
    if (warp >= N) return;
    int beg = __ldg(&rowptr[warp]);
    int end = __ldg(&rowptr[warp + 1]);

    __half2 z = __float2half2_rn(0.f);
    __half2 a0 = z, a1 = z;
    int i = beg;
    for (; i + 3 < end; i += 4) {
        int s0 = __ldg(&eidx[i]);
        int s1 = __ldg(&eidx[i + 1]);
        int s2 = __ldg(&eidx[i + 2]);
        int s3 = __ldg(&eidx[i + 3]);
        const __half2* r0 = p2 + (size_t)s0 * 64 + lane * 2;
        const __half2* r1 = p2 + (size_t)s1 * 64 + lane * 2;
        const __half2* r2 = p2 + (size_t)s2 * 64 + lane * 2;
        const __half2* r3 = p2 + (size_t)s3 * 64 + lane * 2;
        __half2 v00 = r0[0], v01 = r0[1];
        __half2 v10 = r1[0], v11 = r1[1];
        __half2 v20 = r2[0], v21 = r2[1];
        __half2 v30 = r3[0], v31 = r3[1];
        a0 = __hmax2(a0, __hmax2(__hmax2(v00, v10), __hmax2(v20, v30)));
        a1 = __hmax2(a1, __hmax2(__hmax2(v01, v11), __hmax2(v21, v31)));
    }
    for (; i < end; i++) {
        int s = __ldg(&eidx[i]);
        const __half2* r = p2 + (size_t)s * 64 + lane * 2;
        a0 = __hmax2(a0, r[0]);
        a1 = __hmax2(a1, r[1]);
    }
    float2 f0 = __half22float2(a0);
    float2 f1 = __half22float2(a1);
    *(float4*)(agg + (size_t)warp * F + lane * 4) = make_float4(f0.x, f0.y, f1.x, f1.y);
}

// ---------------------------------------------------------------------------
extern "C" void kernel_launch(void* const* d_in, const int* in_sizes, int n_in,
                              void* d_out, int out_size)
{
    const float* x       = (const float*)d_in[0];
    const int*   src     = (const int*)  d_in[1];
    const int*   dst     = (const int*)  d_in[2];
    const float* W_pool1 = (const float*)d_in[3];
    const float* b_pool1 = (const float*)d_in[4];
    const float* W_self1 = (const float*)d_in[5];
    const float* W_neigh1= (const float*)d_in[6];
    const float* b1      = (const float*)d_in[7];
    const float* W_pool2 = (const float*)d_in[8];
    const float* b_pool2 = (const float*)d_in[9];
    const float* W_self2 = (const float*)d_in[10];
    const float* W_neigh2= (const float*)d_in[11];
    const float* b2      = (const float*)d_in[12];

    const int M = in_sizes[0] / F;       // 50000
    const int E = in_sizes[1];           // 1600000

    __half* p;
    float *agg, *h1, *xr, *w;
    int *cnt, *rowptr, *cursor, *eidx, *blksum;
    cudaGetSymbolAddress((void**)&p,      g_p);
    cudaGetSymbolAddress((void**)&agg,    g_agg);
    cudaGetSymbolAddress((void**)&h1,     g_h1);
    cudaGetSymbolAddress((void**)&xr,     g_xr);
    cudaGetSymbolAddress((void**)&w,      g_w);
    cudaGetSymbolAddress((void**)&cnt,    g_cnt);
    cudaGetSymbolAddress((void**)&rowptr, g_rowptr);
    cudaGetSymbolAddress((void**)&cursor, g_cursor);
    cudaGetSymbolAddress((void**)&eidx,   g_eidx);
    cudaGetSymbolAddress((void**)&blksum, g_blksum);
    float* out = (float*)d_out;

    const float* rWp1 = w + 0 * F * F;
    const float* rWs1 = w + 1 * F * F;
    const float* rWn1 = w + 2 * F * F;
    const float* rWp2 = w + 3 * F * F;
    const float* rWs2 = w + 4 * F * F;
    const float* rWn2 = w + 5 * F * F;

    cudaFuncSetAttribute(gemm_tc_kernel<false, false, true, false>,
                         cudaFuncAttributeMaxDynamicSharedMemorySize, SMEM_BYTES);
    cudaFuncSetAttribute(gemm_tc_kernel<true, true, false, true>,
                         cudaFuncAttributeMaxDynamicSharedMemorySize, SMEM_BYTES);
    cudaFuncSetAttribute(gemm_tc_kernel<true, true, false, false>,
                         cudaFuncAttributeMaxDynamicSharedMemorySize, SMEM_BYTES);

    const int gblocks = (M + 63) / 64;
    const int eblocks = (E + 255) / 256;
    const int nb      = (M + SCAN_CHUNK - 1) / SCAN_CHUNK;
    const int wblocks = (M * 32 + 255) / 256;

    // Order chosen so ncu (-s 5) captures the pool GEMM (5th launch).
    round_w_kernel<<<dim3(16, 6), 256>>>(W_pool1, W_self1, W_neigh1,
                                         W_pool2, W_self2, W_neigh2, w);      // 1
    round_x_kernel<<<(M * F / 4 + 255) / 256, 256>>>(x, xr, M * F / 4);       // 2
    cudaMemsetAsync(cnt, 0, (size_t)M * sizeof(int), 0);                      // 3
    hist_kernel<<<eblocks, 256>>>(dst, cnt, E);                               // 4
    gemm_tc_kernel<false, false, true, false><<<gblocks, 256, SMEM_BYTES>>>(  // 5: pool GEMM L1
        xr, rWp1, nullptr, nullptr, b_pool1, p, M);
    scan_block_kernel<<<nb, SCAN_CHUNK>>>(cnt, rowptr, blksum, M);            // 6
    scan_partials_kernel<<<1, 32>>>(blksum, nb);                              // 7
    add_offsets_kernel<<<(M + 256) / 256, 256>>>(rowptr, cursor, blksum, M, E); // 8
    fill_csr_kernel<<<eblocks, 256>>>(src, dst, cursor, eidx, E);             // 9

    // ---- Layer 1 (cont.) ----
    gather_max_kernel<<<wblocks, 256>>>((const __half2*)p, rowptr, eidx, agg, M);
    gemm_tc_kernel<true, true, false, true><<<gblocks, 256, SMEM_BYTES>>>(
        xr, rWs1, agg, rWn1, b1, h1, M);

    // ---- Layer 2 ----
    gemm_tc_kernel<false, false, true, false><<<gblocks, 256, SMEM_BYTES>>>(
        h1, rWp2, nullptr, nullptr, b_pool2, p, M);
    gather_max_kernel<<<wblocks, 256>>>((const __half2*)p, rowptr, eidx, agg, M);
    gemm_tc_kernel<true, true, false, false><<<gblocks, 256, SMEM_BYTES>>>(
        h1, rWs2, agg, rWn2, b2, out, M);
}